// round 10
// baseline (speedup 1.0000x reference)
#include <cuda_runtime.h>
#include <cuda_bf16.h>

#define TOKENS 32768
#define DMODEL 2048
#define NEXP   64
#define KSPLIT 2
#define KPER   (DMODEL / KSPLIT)   // 1024
#define TBLK   64
#define KC     32
#define NCH    (KPER / KC)         // 32
#define NTH    128
#define XP     40                  // smem pitch in bf16 elems (80B)
#define LG_LD  68
#define TBLKB  128                 // tokens per reduce block

// stage layout: x hi/lo then w hi/lo (w filled by one flat cp.async block)
#define XH_OFF 0
#define XL_OFF 5120
#define W_OFF  10240               // [hi 5120 | lo 5120]
#define STAGE  20480
#define SMEM_DYN (2 * STAGE)       // 40 KB

typedef unsigned int u32;
typedef unsigned long long u64;

// pre-split, pre-pitched w tiles: [chunk(64)][hl(2)][row(64)][pitch 20 u32] = 640KB
__device__ u32 g_wtile[64 * 2560];
// partial logits: [split][token][expert] = 16MB
__device__ float g_part[KSPLIT][TOKENS][NEXP];

static __device__ __forceinline__ u32 smem_u32(const void* p) {
    u32 a;
    asm("{ .reg .u64 t; cvta.to.shared.u64 t, %1; cvt.u32.u64 %0, t; }" : "=r"(a) : "l"(p));
    return a;
}

static __device__ __forceinline__ void split4(float4 v, u64& hi, u64& lo) {
    __nv_bfloat162 h01 = __float22bfloat162_rn(make_float2(v.x, v.y));
    __nv_bfloat162 h23 = __float22bfloat162_rn(make_float2(v.z, v.w));
    float2 f01 = __bfloat1622float2(h01);
    float2 f23 = __bfloat1622float2(h23);
    __nv_bfloat162 l01 = __float22bfloat162_rn(make_float2(v.x - f01.x, v.y - f01.y));
    __nv_bfloat162 l23 = __float22bfloat162_rn(make_float2(v.z - f23.x, v.w - f23.y));
    u32 a = *reinterpret_cast<u32*>(&h01);
    u32 b = *reinterpret_cast<u32*>(&h23);
    u32 c = *reinterpret_cast<u32*>(&l01);
    u32 d = *reinterpret_cast<u32*>(&l23);
    hi = (u64)a | ((u64)b << 32);
    lo = (u64)c | ((u64)d << 32);
}

#define LDSM_X4(R, addr)                                                      \
    asm volatile("ldmatrix.sync.aligned.m8n8.x4.shared.b16 {%0,%1,%2,%3}, [%4];" \
        : "=r"((R)[0]), "=r"((R)[1]), "=r"((R)[2]), "=r"((R)[3]) : "r"(addr))

#define MMA_BF16(C, A, B0, B1)                                                \
    asm volatile("mma.sync.aligned.m16n8k16.row.col.f32.bf16.bf16.f32 "       \
        "{%0,%1,%2,%3}, {%4,%5,%6,%7}, {%8,%9}, {%0,%1,%2,%3};"               \
        : "+f"((C)[0]), "+f"((C)[1]), "+f"((C)[2]), "+f"((C)[3])              \
        : "r"((A)[0]), "r"((A)[1]), "r"((A)[2]), "r"((A)[3]), "r"(B0), "r"(B1))

#define CP_ASYNC16(dst, src)                                                  \
    asm volatile("cp.async.cg.shared.global [%0], [%1], 16;" :: "r"(dst), "l"(src))
#define CP_COMMIT()  asm volatile("cp.async.commit_group;" ::: "memory")
#define CP_WAIT0()   asm volatile("cp.async.wait_group 0;" ::: "memory")

// ---- kernel 1: split w into pitched hi/lo chunk tiles ----
__global__ void wsplit_kernel(const float* __restrict__ w) {
    int u = blockIdx.x * blockDim.x + threadIdx.x;   // 640*256 = 163840
    int ch  = u / 2560;
    int r   = u % 2560;
    int hl  = r / 1280;
    int r2  = r % 1280;
    int row = r2 / 20;
    int c2  = r2 % 20;
    u32 outv = 0;
    if (c2 < 16) {
        float2 p = *(const float2*)(w + (size_t)row * DMODEL + ch * KC + c2 * 2);
        __nv_bfloat162 h = __float22bfloat162_rn(p);
        if (hl == 0) outv = *reinterpret_cast<u32*>(&h);
        else {
            float2 f = __bfloat1622float2(h);
            __nv_bfloat162 l = __float22bfloat162_rn(make_float2(p.x - f.x, p.y - f.y));
            outv = *reinterpret_cast<u32*>(&l);
        }
    }
    g_wtile[u] = outv;
}

// ---- kernel 2: K-split GEMM -> partial logits ----
__global__ __launch_bounds__(NTH, 5)
void gemm_kernel(const float* __restrict__ x)
{
    extern __shared__ char dsm[];
    const int tid = threadIdx.x;
    const int wid = tid >> 5;
    const int lid = tid & 31;
    const int t0  = blockIdx.x * TBLK;
    const int ks0 = blockIdx.y;           // K-split index
    const u32 dsm_b = smem_u32(dsm);

    // x staging: 64 rows x 32 k, 128 threads, 4 row-passes
    const int gr = tid >> 3;              // 0..15
    const int gc = tid & 7;
    const float* xbase = x + (size_t)(t0 + gr) * DMODEL + ks0 * KPER + gc * 4;
    const u32 sts_off = (u32)((gr * XP + gc * 4) * 2);

    // w cp.async geometry: 10240B / 128 thr = 80B each
    const char* wsrc0 = (const char*)g_wtile + (size_t)ks0 * NCH * 10240 + tid * 80;
    const u32 wdst0 = dsm_b + W_OFF + tid * 80;

    // warp tile 32x32 over 64x64
    const int wtok0 = (wid >> 1) * 32;
    const int wexp0 = (wid & 1) * 32;
    const int arow = (lid & 7) + ((lid >> 3) & 1) * 8;
    const int acol = ((lid >> 4) & 1) * 8;
    const int brow = (lid & 7) + ((lid >> 4) & 1) * 8;
    const int bcol = ((lid >> 3) & 1) * 8;
    const u32 a_off = (u32)(((wtok0 + arow) * XP + acol) * 2);
    const u32 b_off = (u32)(((wexp0 + brow) * XP + bcol) * 2);

    float acc[2][4][4];
    #pragma unroll
    for (int mt = 0; mt < 2; mt++)
        #pragma unroll
        for (int nt = 0; nt < 4; nt++)
            #pragma unroll
            for (int c = 0; c < 4; c++)
                acc[mt][nt][c] = 0.0f;

    float4 xr[4];

    // ---- prologue: w chunk0 via cp.async (G0); x chunk0 staged; x chunk1 in regs
    #pragma unroll
    for (int i = 0; i < 5; i++) CP_ASYNC16(wdst0 + i * 16, wsrc0 + i * 16);
    CP_COMMIT();
    #pragma unroll
    for (int i = 0; i < 4; i++) xr[i] = *(const float4*)(xbase + (size_t)i * 16 * DMODEL);
    {
        char* st = dsm;
        #pragma unroll
        for (int i = 0; i < 4; i++) {
            u64 hi, lo; split4(xr[i], hi, lo);
            u32 o = sts_off + i * 16 * XP * 2;
            *(u64*)(st + XH_OFF + o) = hi;
            *(u64*)(st + XL_OFF + o) = lo;
        }
    }
    #pragma unroll
    for (int i = 0; i < 4; i++) xr[i] = *(const float4*)(xbase + KC + (size_t)i * 16 * DMODEL);

    for (int ch = 0; ch < NCH; ++ch) {
        CP_WAIT0();          // w for stage ch complete (issued last iter)
        __syncthreads();     // all staging visible; next stage writable

        if (ch + 1 < NCH) {
            // w chunk ch+1 -> stage(ch+1) via cp.async (no regs)
            const char* ws = wsrc0 + (size_t)(ch + 1) * 10240;
            const u32 wd = wdst0 + ((ch + 1) & 1) * STAGE;
            #pragma unroll
            for (int i = 0; i < 5; i++) CP_ASYNC16(wd + i * 16, ws + i * 16);
            CP_COMMIT();
            // x chunk ch+1 -> stage(ch+1)
            char* st = dsm + ((ch + 1) & 1) * STAGE;
            #pragma unroll
            for (int i = 0; i < 4; i++) {
                u64 hi, lo; split4(xr[i], hi, lo);
                u32 o = sts_off + i * 16 * XP * 2;
                *(u64*)(st + XH_OFF + o) = hi;
                *(u64*)(st + XL_OFF + o) = lo;
            }
        }
        if (ch + 2 < NCH) {
            const int k0 = (ch + 2) * KC;
            #pragma unroll
            for (int i = 0; i < 4; i++)
                xr[i] = *(const float4*)(xbase + k0 + (size_t)i * 16 * DMODEL);
        }

        const u32 sb = dsm_b + (ch & 1) * STAGE;
        const u32 ah_b = sb + XH_OFF + a_off;
        const u32 al_b = sb + XL_OFF + a_off;
        const u32 bh_b = sb + W_OFF + b_off;          // hi tile
        const u32 bl_b = sb + W_OFF + 5120 + b_off;   // lo tile

        #pragma unroll
        for (int ks = 0; ks < KC / 16; ks++) {
            const u32 ko = ks * 32;
            u32 bh[8], bl[8];
            #pragma unroll
            for (int ng = 0; ng < 2; ng++) {
                LDSM_X4(bh + ng * 4, bh_b + ng * (16 * XP * 2) + ko);
                LDSM_X4(bl + ng * 4, bl_b + ng * (16 * XP * 2) + ko);
            }
            // A frags per mt (keeps live A regs at 8)
            #pragma unroll
            for (int mt = 0; mt < 2; mt++) {
                u32 ah[4], al[4];
                LDSM_X4(ah, ah_b + mt * (16 * XP * 2) + ko);
                LDSM_X4(al, al_b + mt * (16 * XP * 2) + ko);
                #pragma unroll
                for (int nt = 0; nt < 4; nt++) {
                    u32 b0h = bh[nt * 2], b1h = bh[nt * 2 + 1];
                    MMA_BF16(acc[mt][nt], ah, b0h, b1h);                      // hi*hi
                    MMA_BF16(acc[mt][nt], al, b0h, b1h);                      // lo*hi
                    MMA_BF16(acc[mt][nt], ah, bl[nt * 2], bl[nt * 2 + 1]);    // hi*lo
                }
            }
        }
    }

    // ---- store partial logits straight from regs ----
    {
        const int crow = lid >> 2;
        const int ccol = (lid & 3) * 2;
        float* pb = &g_part[ks0][0][0];
        #pragma unroll
        for (int mt = 0; mt < 2; mt++)
            #pragma unroll
            for (int nt = 0; nt < 4; nt++) {
                int tok = t0 + wtok0 + mt * 16 + crow;
                int ex  = wexp0 + nt * 8 + ccol;
                *(float2*)&pb[(size_t)tok * NEXP + ex] =
                    make_float2(acc[mt][nt][0], acc[mt][nt][1]);
                *(float2*)&pb[(size_t)(tok + 8) * NEXP + ex] =
                    make_float2(acc[mt][nt][2], acc[mt][nt][3]);
            }
    }
}

// ---- kernel 3: reduce halves + softmax + top-2 + outputs ----
__global__ __launch_bounds__(256)
void reduce_kernel(float* __restrict__ out)
{
    __shared__ float logits[TBLKB * LG_LD];
    __shared__ float inv_s[TBLKB];
    const int tid = threadIdx.x;
    const int t0  = blockIdx.x * TBLKB;

    // coalesced load+add of both partial halves
    const float4* p0 = (const float4*)&g_part[0][t0][0];
    const float4* p1 = (const float4*)&g_part[1][t0][0];
    for (int f = tid; f < TBLKB * (NEXP / 4); f += 256) {
        int t = f >> 4, c4 = f & 15;
        float4 a = p0[f], b = p1[f];
        *(float4*)&logits[t * LG_LD + c4 * 4] =
            make_float4(a.x + b.x, a.y + b.y, a.z + b.z, a.w + b.w);
    }
    __syncthreads();

    if (tid < TBLKB) {
        const int t = tid;
        float* row = &logits[t * LG_LD];

        float m1 = -3.4e38f, m2 = -3.4e38f;
        int   i1 = 0,        i2 = 0;
        #pragma unroll
        for (int e = 0; e < NEXP; e++) {
            float v = row[e];
            if (v > m1)      { m2 = m1; i2 = i1; m1 = v; i1 = e; }
            else if (v > m2) { m2 = v; i2 = e; }
        }

        float s = 0.0f;
        #pragma unroll
        for (int e = 0; e < NEXP; e++) {
            float ev = __expf(row[e] - m1);
            row[e] = ev;
            s += ev;
        }
        inv_s[t] = 1.0f / s;

        float e2v = __expf(m2 - m1);
        float g1  = 1.0f / (1.0f + e2v);

        int gt = t0 + t;
        out[2 * gt + 0] = g1;
        out[2 * gt + 1] = e2v * g1;
        float* oidx = out + (size_t)2 * TOKENS;
        oidx[2 * gt + 0] = (float)i1;
        oidx[2 * gt + 1] = (float)i2;
    }
    __syncthreads();

    float* oprob = out + (size_t)4 * TOKENS;
    for (int f = tid; f < TBLKB * (NEXP / 4); f += 256) {
        int r = f >> 4, c4 = f & 15;
        float4 ev = *(const float4*)&logits[r * LG_LD + c4 * 4];
        float inv = inv_s[r];
        float4 p = make_float4(ev.x * inv, ev.y * inv, ev.z * inv, ev.w * inv);
        *(float4*)&oprob[(size_t)(t0 + r) * NEXP + c4 * 4] = p;
    }
}

extern "C" void kernel_launch(void* const* d_in, const int* in_sizes, int n_in,
                              void* d_out, int out_size) {
    const float* x = (const float*)d_in[0];
    const float* w = (const float*)d_in[1];
    float* out = (float*)d_out;
    wsplit_kernel<<<640, 256>>>(w);
    cudaFuncSetAttribute(gemm_kernel,
                         cudaFuncAttributeMaxDynamicSharedMemorySize, SMEM_DYN);
    gemm_kernel<<<dim3(TOKENS / TBLK, KSPLIT), NTH, SMEM_DYN>>>(x);
    reduce_kernel<<<TOKENS / TBLKB, 256>>>(out);
}